// round 8
// baseline (speedup 1.0000x reference)
#include <cuda_runtime.h>

#define PAD_ID    100000
#define ITEM_ROWS 100001
#define D   64
#define NB  4096
#define L   200
#define NQUAD (L / 4)          // 50 index quads per user
#define NEGW 0.1f

#define NB_G1   296            // item Gram blocks
#define NB_GV   32             // user Gram blocks
#define NB_GRAM (NB_G1 + NB_GV)   // 328
#define NB_POS  1024           // pos-loss blocks
#define B_PER_BLK 4
#define CHUNK   64
#define GRID_TOTAL (NB_GRAM + NB_POS)   // 1352

// zero-initialized at module load; last block resets them each run
__device__ float g_g1[D * D];
__device__ float g_gv[D * D];
__device__ float g_pos;
__device__ unsigned int g_done;

__device__ __forceinline__ float dot8(float4 a0, float4 a1, float4 b0, float4 b1) {
    float s = a0.x * b0.x;
    s = fmaf(a0.y, b0.y, s);
    s = fmaf(a0.z, b0.z, s);
    s = fmaf(a0.w, b0.w, s);
    s = fmaf(a1.x, b1.x, s);
    s = fmaf(a1.y, b1.y, s);
    s = fmaf(a1.z, b1.z, s);
    s = fmaf(a1.w, b1.w, s);
    return s;
}

__global__ __launch_bounds__(256) void enmf_kernel(
    const int* __restrict__ uids, const int* __restrict__ pos_iids,
    const float* __restrict__ userW, const float* __restrict__ itemW,
    const float* __restrict__ h, float* __restrict__ out)
{
    __shared__ float sm[CHUNK * D];   // 16 KB, reused by all paths
    __shared__ float hh[D];
    __shared__ float warpsum[8];
    __shared__ unsigned int s_rank;

    const int tid = threadIdx.x;
    const int bid = blockIdx.x;
    if (tid < D) hh[tid] = h[tid];
    __syncthreads();

    // ---- interleave block types so FMA-bound and L2-bound blocks co-reside ----
    int gram_id = -1, pos_id = -1;
    if (bid < NB_GRAM * 4) {
        if ((bid & 3) == 3) gram_id = bid >> 2;
        else                pos_id  = (bid >> 2) * 3 + (bid & 3);
    } else {
        pos_id = NB_GRAM * 3 + (bid - NB_GRAM * 4);
    }

    if (gram_id >= 0) {
        // ================= Gram path (upper triangle only) =================
        const bool is_item   = (gram_id < NB_G1);
        const int rows_total = is_item ? ITEM_ROWS : NB;
        const int nblk       = is_item ? NB_G1 : NB_GV;
        const int gb         = is_item ? gram_id : gram_id - NB_G1;
        const int per        = (rows_total + nblk - 1) / nblk;
        const int r0         = gb * per;
        const int r1         = min(r0 + per, rows_total);

        // map tid -> upper-triangle 4x4 tile (ti <= tj) of the 16x16 tile grid
        const bool active = (tid < 136);
        int ti = 0, tj = 0;
        if (active) {
            int tt = tid;
            while (tt >= 16 - ti) { tt -= 16 - ti; ti++; }
            tj = ti + tt;
        }

        float c[4][4];
        #pragma unroll
        for (int i = 0; i < 4; i++)
            #pragma unroll
            for (int j = 0; j < 4; j++) c[i][j] = 0.f;

        float4* smv = (float4*)sm;
        const float4* hv4 = (const float4*)hh;

        for (int base = r0; base < r1; base += CHUNK) {
            for (int i = tid; i < CHUNK * 16; i += 256) {
                int r = base + (i >> 4);
                float4 v = make_float4(0.f, 0.f, 0.f, 0.f);
                if (r < r1) {
                    if (is_item) {
                        v = ((const float4*)itemW)[(size_t)r * 16 + (i & 15)];
                    } else {
                        float4 u = ((const float4*)userW)[(size_t)uids[r] * 16 + (i & 15)];
                        float4 hx = hv4[i & 15];
                        v = make_float4(u.x * hx.x, u.y * hx.y, u.z * hx.z, u.w * hx.w);
                    }
                }
                smv[i] = v;
            }
            __syncthreads();

            if (active) {
                #pragma unroll 8
                for (int r = 0; r < CHUNK; r++) {
                    float4 a = smv[r * 16 + ti];
                    float4 b = smv[r * 16 + tj];
                    float av[4] = {a.x, a.y, a.z, a.w};
                    float bv[4] = {b.x, b.y, b.z, b.w};
                    #pragma unroll
                    for (int i = 0; i < 4; i++)
                        #pragma unroll
                        for (int j = 0; j < 4; j++)
                            c[i][j] = fmaf(av[i], bv[j], c[i][j]);
                }
            }
            __syncthreads();
        }

        if (active) {
            float* dst = is_item ? g_g1 : g_gv;
            #pragma unroll
            for (int i = 0; i < 4; i++)
                #pragma unroll
                for (int j = 0; j < 4; j++) {
                    if (!(ti == tj && j < i))   // store strict upper triangle only
                        atomicAdd(&dst[(ti * 4 + i) * D + (tj * 4 + j)], c[i][j]);
                }
        }
    } else {
        // ===== pos-loss path: 8 lanes/row, 2 users per iter, 3-shfl reduce =====
        const int b0 = pos_id * B_PER_BLK;

        for (int i = tid; i < B_PER_BLK * D; i += 256) {
            int bl = i >> 6, d = i & 63;
            sm[i] = userW[(size_t)uids[b0 + bl] * D + d] * hh[d];
        }
        __syncthreads();

        const int warp = tid >> 5, lane = tid & 31;
        const int g    = lane >> 3;     // row group 0..3 within warp
        const int sub  = lane & 7;      // 8 lanes per row
        float acc = 0.f;

        for (int blp = 0; blp < B_PER_BLK; blp += 2) {
            // 8-dim slices of v for the two users (two float4s each)
            const float4* vra = (const float4*)(sm + blp * D);
            const float4* vrb = (const float4*)(sm + (blp + 1) * D);
            float4 vA0 = vra[sub], vA1 = vra[8 + sub];
            float4 vB0 = vrb[sub], vB1 = vrb[8 + sub];
            const int* piA = pos_iids + (size_t)(b0 + blp) * L;
            const int* piB = pos_iids + (size_t)(b0 + blp + 1) * L;

            // warp handles quad q of userA AND quad q of userB -> 8 rows/iter
            for (int q = warp; q < NQUAD; q += 8) {
                int4 iA = ((const int4*)piA)[q];
                int4 iB = ((const int4*)piB)[q];
                int ia = (g == 0) ? iA.x : (g == 1) ? iA.y : (g == 2) ? iA.z : iA.w;
                int ib = (g == 0) ? iB.x : (g == 1) ? iB.y : (g == 2) ? iB.z : iB.w;

                float pa = 0.f, pb = 0.f;
                if (ia != PAD_ID) {
                    const float4* r = (const float4*)(itemW + (size_t)ia * D);
                    pa = dot8(r[sub], r[8 + sub], vA0, vA1);
                }
                if (ib != PAD_ID) {
                    const float4* r = (const float4*)(itemW + (size_t)ib * D);
                    pb = dot8(r[sub], r[8 + sub], vB0, vB1);
                }
                // 3-level butterfly within each 8-lane group (4 rows in parallel)
                #pragma unroll
                for (int o = 4; o > 0; o >>= 1) {
                    pa += __shfl_xor_sync(0xffffffffu, pa, o);
                    pb += __shfl_xor_sync(0xffffffffu, pb, o);
                }
                if (sub == 0)
                    acc += (1.0f - NEGW) * (pa * pa + pb * pb) - 2.0f * (pa + pb);
            }
        }

        // acc nonzero only on sub==0 lanes; one butterfly sums the warp
        #pragma unroll
        for (int o = 16; o > 0; o >>= 1)
            acc += __shfl_xor_sync(0xffffffffu, acc, o);
        if (lane == 0) warpsum[warp] = acc;
        __syncthreads();
        if (tid == 0) {
            float s = 0.f;
            #pragma unroll
            for (int w = 0; w < 8; w++) s += warpsum[w];
            atomicAdd(&g_pos, s);
        }
    }

    // ================= last block combines + resets =================
    __threadfence();
    __syncthreads();
    if (tid == 0) s_rank = atomicAdd(&g_done, 1u);
    __syncthreads();

    if (s_rank == GRID_TOTAL - 1) {
        volatile float* v1 = g_g1;
        volatile float* v2 = g_gv;
        float s = 0.f;
        for (int e = tid; e < D * D; e += 256) {
            int i = e >> 6, j = e & 63;
            float w = (i == j) ? 1.f : 2.f;     // mirror the strict upper triangle
            s += w * v1[e] * v2[e];
        }
        sm[tid] = s;
        __syncthreads();
        for (int off = 128; off > 0; off >>= 1) {
            if (tid < off) sm[tid] += sm[tid + off];
            __syncthreads();
        }
        if (tid == 0) {
            out[0] = NEGW * sm[0] + *(volatile float*)&g_pos;
            g_pos = 0.f;
            g_done = 0u;
        }
        for (int e = tid; e < D * D; e += 256) { g_g1[e] = 0.f; g_gv[e] = 0.f; }
    }
}

extern "C" void kernel_launch(void* const* d_in, const int* in_sizes, int n_in,
                              void* d_out, int out_size) {
    const int*   uids     = (const int*)d_in[0];
    const int*   pos_iids = (const int*)d_in[1];
    const float* userW    = (const float*)d_in[2];
    const float* itemW    = (const float*)d_in[3];
    const float* h        = (const float*)d_in[4];
    float* out = (float*)d_out;

    enmf_kernel<<<GRID_TOTAL, 256>>>(uids, pos_iids, userW, itemW, h, out);
}

// round 9
// speedup vs baseline: 1.5321x; 1.5321x over previous
#include <cuda_runtime.h>

#define PAD_ID    100000
#define ITEM_ROWS 100001
#define D   64
#define NB  4096
#define L   200
#define NQUAD (L / 4)
#define NEGW 0.1f

#define NB_G1   296            // item Gram blocks
#define NB_GV   32             // user Gram blocks
#define NB_GRAM (NB_G1 + NB_GV)   // 328
#define NB_POS  1024           // pos-loss blocks
#define B_PER_BLK 4
#define CHUNK   64
#define GRID_TOTAL (NB_GRAM + NB_POS)   // 1352

// zero-initialized at module load; last block resets them each run
__device__ float g_g1[D * D];
__device__ float g_gv[D * D];
__device__ float g_pos;
__device__ unsigned int g_done;

__global__ __launch_bounds__(256) void enmf_kernel(
    const int* __restrict__ uids, const int* __restrict__ pos_iids,
    const float* __restrict__ userW, const float* __restrict__ itemW,
    const float* __restrict__ h, float* __restrict__ out)
{
    __shared__ float sm[2 * CHUNK * D];   // 32 KB double buffer (Gram); pos uses buf 0
    __shared__ float hh[D];
    __shared__ float warpsum[8];
    __shared__ unsigned int s_rank;

    const int tid = threadIdx.x;
    const int bid = blockIdx.x;
    if (tid < D) hh[tid] = h[tid];
    __syncthreads();

    // ---- interleave block types so FMA-bound and L2-bound blocks co-reside ----
    int gram_id = -1, pos_id = -1;
    if (bid < NB_GRAM * 4) {
        if ((bid & 3) == 3) gram_id = bid >> 2;
        else                pos_id  = (bid >> 2) * 3 + (bid & 3);
    } else {
        pos_id = NB_GRAM * 3 + (bid - NB_GRAM * 4);
    }

    if (gram_id >= 0) {
        // ========= Gram path: upper triangle, double-buffered pipeline =========
        const bool is_item   = (gram_id < NB_G1);
        const int rows_total = is_item ? ITEM_ROWS : NB;
        const int nblk       = is_item ? NB_G1 : NB_GV;
        const int gb         = is_item ? gram_id : gram_id - NB_G1;
        const int per        = (rows_total + nblk - 1) / nblk;
        const int r0         = gb * per;
        const int r1         = min(r0 + per, rows_total);

        const bool compute_thread = (tid < 136);
        int ti = 0, tj = 0;
        if (compute_thread) {
            int tt = tid;
            while (tt >= 16 - ti) { tt -= 16 - ti; ti++; }
            tj = ti + tt;
        }

        float c[4][4];
        #pragma unroll
        for (int i = 0; i < 4; i++)
            #pragma unroll
            for (int j = 0; j < 4; j++) c[i][j] = 0.f;

        float4* smv = (float4*)sm;
        const float4* hv4 = (const float4*)hh;

        // fill helper inlined: fills buffer buf with rows [base, base+CHUNK)
        // using threads [lo, 256) striding (256-lo)
        auto fill = [&](int buf, int base, int lo) {
            for (int i = tid - lo; i < CHUNK * 16; i += 256 - lo) {
                if (i < 0) continue;
                int r = base + (i >> 4);
                float4 v = make_float4(0.f, 0.f, 0.f, 0.f);
                if (r < r1) {
                    if (is_item) {
                        v = ((const float4*)itemW)[(size_t)r * 16 + (i & 15)];
                    } else {
                        float4 u = ((const float4*)userW)[(size_t)uids[r] * 16 + (i & 15)];
                        float4 hx = hv4[i & 15];
                        v = make_float4(u.x * hx.x, u.y * hx.y, u.z * hx.z, u.w * hx.w);
                    }
                }
                smv[buf * CHUNK * 16 + i] = v;
            }
        };

        // prologue: everyone fills buffer 0
        fill(0, r0, 0);
        __syncthreads();

        int buf = 0;
        for (int base = r0; base < r1; base += CHUNK, buf ^= 1) {
            // fill threads stage the next chunk while compute threads work
            if (!compute_thread) {
                if (base + CHUNK < r1) fill(buf ^ 1, base + CHUNK, 136);
            } else {
                const float4* cb = smv + buf * CHUNK * 16;
                #pragma unroll 8
                for (int r = 0; r < CHUNK; r++) {
                    float4 a = cb[r * 16 + ti];
                    float4 b = cb[r * 16 + tj];
                    float av[4] = {a.x, a.y, a.z, a.w};
                    float bv[4] = {b.x, b.y, b.z, b.w};
                    #pragma unroll
                    for (int i = 0; i < 4; i++)
                        #pragma unroll
                        for (int j = 0; j < 4; j++)
                            c[i][j] = fmaf(av[i], bv[j], c[i][j]);
                }
            }
            __syncthreads();
        }

        if (compute_thread) {
            float* dst = is_item ? g_g1 : g_gv;
            #pragma unroll
            for (int i = 0; i < 4; i++)
                #pragma unroll
                for (int j = 0; j < 4; j++) {
                    if (!(ti == tj && j < i))   // store strict upper triangle only
                        atomicAdd(&dst[(ti * 4 + i) * D + (tj * 4 + j)], c[i][j]);
                }
        }
    } else {
        // ===== pos-loss path: all 4 users per iteration, 20 loads in flight =====
        const int b0 = pos_id * B_PER_BLK;

        for (int i = tid; i < B_PER_BLK * D; i += 256) {
            int bl = i >> 6, d = i & 63;
            sm[i] = userW[(size_t)uids[b0 + bl] * D + d] * hh[d];
        }
        __syncthreads();

        const int warp = tid >> 5, lane = tid & 31;
        float acc = 0.f;

        float2 v0 = ((const float2*)(sm + 0 * D))[lane];
        float2 v1 = ((const float2*)(sm + 1 * D))[lane];
        float2 v2 = ((const float2*)(sm + 2 * D))[lane];
        float2 v3 = ((const float2*)(sm + 3 * D))[lane];
        const int4* pi0 = (const int4*)(pos_iids + (size_t)(b0 + 0) * L);
        const int4* pi1 = (const int4*)(pos_iids + (size_t)(b0 + 1) * L);
        const int4* pi2 = (const int4*)(pos_iids + (size_t)(b0 + 2) * L);
        const int4* pi3 = (const int4*)(pos_iids + (size_t)(b0 + 3) * L);

        for (int q = warp; q < NQUAD; q += 8) {
            int4 iA = pi0[q];
            int4 iB = pi1[q];
            int4 iC = pi2[q];
            int4 iD = pi3[q];

            // 16 independent gathers issued before any reduction
            float2 z = make_float2(0.f, 0.f);
            float2 rA0 = z, rA1 = z, rA2 = z, rA3 = z;
            float2 rB0 = z, rB1 = z, rB2 = z, rB3 = z;
            float2 rC0 = z, rC1 = z, rC2 = z, rC3 = z;
            float2 rD0 = z, rD1 = z, rD2 = z, rD3 = z;
            if (iA.x != PAD_ID) rA0 = ((const float2*)(itemW + (size_t)iA.x * D))[lane];
            if (iA.y != PAD_ID) rA1 = ((const float2*)(itemW + (size_t)iA.y * D))[lane];
            if (iA.z != PAD_ID) rA2 = ((const float2*)(itemW + (size_t)iA.z * D))[lane];
            if (iA.w != PAD_ID) rA3 = ((const float2*)(itemW + (size_t)iA.w * D))[lane];
            if (iB.x != PAD_ID) rB0 = ((const float2*)(itemW + (size_t)iB.x * D))[lane];
            if (iB.y != PAD_ID) rB1 = ((const float2*)(itemW + (size_t)iB.y * D))[lane];
            if (iB.z != PAD_ID) rB2 = ((const float2*)(itemW + (size_t)iB.z * D))[lane];
            if (iB.w != PAD_ID) rB3 = ((const float2*)(itemW + (size_t)iB.w * D))[lane];
            if (iC.x != PAD_ID) rC0 = ((const float2*)(itemW + (size_t)iC.x * D))[lane];
            if (iC.y != PAD_ID) rC1 = ((const float2*)(itemW + (size_t)iC.y * D))[lane];
            if (iC.z != PAD_ID) rC2 = ((const float2*)(itemW + (size_t)iC.z * D))[lane];
            if (iC.w != PAD_ID) rC3 = ((const float2*)(itemW + (size_t)iC.w * D))[lane];
            if (iD.x != PAD_ID) rD0 = ((const float2*)(itemW + (size_t)iD.x * D))[lane];
            if (iD.y != PAD_ID) rD1 = ((const float2*)(itemW + (size_t)iD.y * D))[lane];
            if (iD.z != PAD_ID) rD2 = ((const float2*)(itemW + (size_t)iD.z * D))[lane];
            if (iD.w != PAD_ID) rD3 = ((const float2*)(itemW + (size_t)iD.w * D))[lane];

            float a0 = fmaf(rA0.x, v0.x, rA0.y * v0.y);
            float a1 = fmaf(rA1.x, v0.x, rA1.y * v0.y);
            float a2 = fmaf(rA2.x, v0.x, rA2.y * v0.y);
            float a3 = fmaf(rA3.x, v0.x, rA3.y * v0.y);
            float b0f = fmaf(rB0.x, v1.x, rB0.y * v1.y);
            float b1f = fmaf(rB1.x, v1.x, rB1.y * v1.y);
            float b2f = fmaf(rB2.x, v1.x, rB2.y * v1.y);
            float b3f = fmaf(rB3.x, v1.x, rB3.y * v1.y);
            float c0 = fmaf(rC0.x, v2.x, rC0.y * v2.y);
            float c1 = fmaf(rC1.x, v2.x, rC1.y * v2.y);
            float c2 = fmaf(rC2.x, v2.x, rC2.y * v2.y);
            float c3 = fmaf(rC3.x, v2.x, rC3.y * v2.y);
            float d0 = fmaf(rD0.x, v3.x, rD0.y * v3.y);
            float d1 = fmaf(rD1.x, v3.x, rD1.y * v3.y);
            float d2 = fmaf(rD2.x, v3.x, rD2.y * v3.y);
            float d3 = fmaf(rD3.x, v3.x, rD3.y * v3.y);

            // 16 interleaved butterfly trees
            #pragma unroll
            for (int o = 16; o > 0; o >>= 1) {
                a0 += __shfl_xor_sync(0xffffffffu, a0, o);
                b0f += __shfl_xor_sync(0xffffffffu, b0f, o);
                c0 += __shfl_xor_sync(0xffffffffu, c0, o);
                d0 += __shfl_xor_sync(0xffffffffu, d0, o);
                a1 += __shfl_xor_sync(0xffffffffu, a1, o);
                b1f += __shfl_xor_sync(0xffffffffu, b1f, o);
                c1 += __shfl_xor_sync(0xffffffffu, c1, o);
                d1 += __shfl_xor_sync(0xffffffffu, d1, o);
                a2 += __shfl_xor_sync(0xffffffffu, a2, o);
                b2f += __shfl_xor_sync(0xffffffffu, b2f, o);
                c2 += __shfl_xor_sync(0xffffffffu, c2, o);
                d2 += __shfl_xor_sync(0xffffffffu, d2, o);
                a3 += __shfl_xor_sync(0xffffffffu, a3, o);
                b3f += __shfl_xor_sync(0xffffffffu, b3f, o);
                c3 += __shfl_xor_sync(0xffffffffu, c3, o);
                d3 += __shfl_xor_sync(0xffffffffu, d3, o);
            }
            float sq = a0*a0 + a1*a1 + a2*a2 + a3*a3
                     + b0f*b0f + b1f*b1f + b2f*b2f + b3f*b3f
                     + c0*c0 + c1*c1 + c2*c2 + c3*c3
                     + d0*d0 + d1*d1 + d2*d2 + d3*d3;
            float ln = a0 + a1 + a2 + a3 + b0f + b1f + b2f + b3f
                     + c0 + c1 + c2 + c3 + d0 + d1 + d2 + d3;
            acc = fmaf(1.0f - NEGW, sq, fmaf(-2.0f, ln, acc));
        }

        // acc identical on all lanes after butterflies — take lane 0 once
        if (lane == 0) warpsum[warp] = acc;
        __syncthreads();
        if (tid == 0) {
            float s = 0.f;
            #pragma unroll
            for (int w = 0; w < 8; w++) s += warpsum[w];
            atomicAdd(&g_pos, s);
        }
    }

    // ================= last block combines + resets =================
    __threadfence();
    __syncthreads();
    if (tid == 0) s_rank = atomicAdd(&g_done, 1u);
    __syncthreads();

    if (s_rank == GRID_TOTAL - 1) {
        volatile float* v1 = g_g1;
        volatile float* v2 = g_gv;
        float s = 0.f;
        for (int e = tid; e < D * D; e += 256) {
            int i = e >> 6, j = e & 63;
            float w = (i == j) ? 1.f : 2.f;     // mirror the strict upper triangle
            s += w * v1[e] * v2[e];
        }
        sm[tid] = s;
        __syncthreads();
        for (int off = 128; off > 0; off >>= 1) {
            if (tid < off) sm[tid] += sm[tid + off];
            __syncthreads();
        }
        if (tid == 0) {
            out[0] = NEGW * sm[0] + *(volatile float*)&g_pos;
            g_pos = 0.f;
            g_done = 0u;
        }
        for (int e = tid; e < D * D; e += 256) { g_g1[e] = 0.f; g_gv[e] = 0.f; }
    }
}

extern "C" void kernel_launch(void* const* d_in, const int* in_sizes, int n_in,
                              void* d_out, int out_size) {
    const int*   uids     = (const int*)d_in[0];
    const int*   pos_iids = (const int*)d_in[1];
    const float* userW    = (const float*)d_in[2];
    const float* itemW    = (const float*)d_in[3];
    const float* h        = (const float*)d_in[4];
    float* out = (float*)d_out;

    enmf_kernel<<<GRID_TOTAL, 256>>>(uids, pos_iids, userW, itemW, h, out);
}

// round 10
// speedup vs baseline: 1.9391x; 1.2656x over previous
#include <cuda_runtime.h>
#include <cstdint>

#define PAD_ID    100000
#define ITEM_ROWS 100001
#define D   64
#define NB  4096
#define L   200
#define NQUAD (L / 4)
#define NEGW 0.1f

#define NB_G1   296            // item Gram blocks
#define NB_GV   32             // user Gram blocks
#define NB_GRAM (NB_G1 + NB_GV)   // 328
#define NB_POS  1024           // pos-loss blocks
#define B_PER_BLK 4
#define CHUNK   64
#define STRIDE  72             // 8*row+col mod 32 -> conflict-free fragment loads
#define GRID_TOTAL (NB_GRAM + NB_POS)   // 1352

// zero-initialized at module load; last block resets them each run
__device__ float g_g1[D * D];
__device__ float g_gv[D * D];
__device__ float g_pos;
__device__ unsigned int g_done;

__device__ __forceinline__ float tf32r(float x) {
    uint32_t r;
    asm("cvt.rna.tf32.f32 %0, %1;" : "=r"(r) : "f"(x));
    return __uint_as_float(r);
}

__device__ __forceinline__ void mma_tf32(float d[4], uint32_t a0, uint32_t a1,
                                         uint32_t a2, uint32_t a3,
                                         uint32_t b0, uint32_t b1) {
    asm volatile(
        "mma.sync.aligned.m16n8k8.row.col.f32.tf32.tf32.f32 "
        "{%0,%1,%2,%3}, {%4,%5,%6,%7}, {%8,%9}, {%0,%1,%2,%3};\n"
        : "+f"(d[0]), "+f"(d[1]), "+f"(d[2]), "+f"(d[3])
        : "r"(a0), "r"(a1), "r"(a2), "r"(a3), "r"(b0), "r"(b1));
}

__global__ __launch_bounds__(256) void enmf_kernel(
    const int* __restrict__ uids, const int* __restrict__ pos_iids,
    const float* __restrict__ userW, const float* __restrict__ itemW,
    const float* __restrict__ h, float* __restrict__ out)
{
    __shared__ float smA[2][CHUNK][STRIDE];   // 36 KB double buffer (Gram)
    __shared__ float hh[D];
    __shared__ float warpsum[8];
    __shared__ unsigned int s_rank;

    float* smf = &smA[0][0][0];               // flat view for pos path / combine

    const int tid = threadIdx.x;
    const int bid = blockIdx.x;
    if (tid < D) hh[tid] = h[tid];
    __syncthreads();

    // ---- interleave block types so tensor/mem-bound blocks co-reside ----
    int gram_id = -1, pos_id = -1;
    if (bid < NB_GRAM * 4) {
        if ((bid & 3) == 3) gram_id = bid >> 2;
        else                pos_id  = (bid >> 2) * 3 + (bid & 3);
    } else {
        pos_id = NB_GRAM * 3 + (bid - NB_GRAM * 4);
    }

    if (gram_id >= 0) {
        // ========= Gram path: tf32 mma, double-buffered fill =========
        const bool is_item   = (gram_id < NB_G1);
        const int rows_total = is_item ? ITEM_ROWS : NB;
        const int nblk       = is_item ? NB_G1 : NB_GV;
        const int gb         = is_item ? gram_id : gram_id - NB_G1;
        const int per        = (rows_total + nblk - 1) / nblk;
        const int r0         = gb * per;
        const int r1         = min(r0 + per, rows_total);

        const int warp = tid >> 5, lane = tid & 31;
        const int gid  = lane >> 2;       // 0..7
        const int tig  = lane & 3;        // 0..3
        const bool compute_warp = (warp < 4);
        const int Ibase = warp * 16;      // compute warps only

        float dacc[8][4];
        #pragma unroll
        for (int n = 0; n < 8; n++)
            #pragma unroll
            for (int k = 0; k < 4; k++) dacc[n][k] = 0.f;

        const float4* hv4 = (const float4*)hh;

        // fill rows [base, base+CHUNK) of buffer buf, tf32-rounded,
        // using threads [lo, 256)
        auto fill = [&](int buf, int base, int lo) {
            for (int i = tid - lo; i < CHUNK * 16; i += 256 - lo) {
                if (i < 0) continue;
                int r = base + (i >> 4);
                int c4 = i & 15;
                float4 v = make_float4(0.f, 0.f, 0.f, 0.f);
                if (r < r1) {
                    if (is_item) {
                        v = ((const float4*)itemW)[(size_t)r * 16 + c4];
                    } else {
                        float4 u = ((const float4*)userW)[(size_t)uids[r] * 16 + c4];
                        float4 hx = hv4[c4];
                        v = make_float4(u.x * hx.x, u.y * hx.y, u.z * hx.z, u.w * hx.w);
                    }
                    v.x = tf32r(v.x); v.y = tf32r(v.y);
                    v.z = tf32r(v.z); v.w = tf32r(v.w);
                }
                ((float4*)&smA[buf][i >> 4][0])[c4] = v;
            }
        };

        fill(0, r0, 0);
        __syncthreads();

        int buf = 0;
        for (int base = r0; base < r1; base += CHUNK, buf ^= 1) {
            if (!compute_warp) {
                if (base + CHUNK < r1) fill(buf ^ 1, base + CHUNK, 128);
            } else {
                #pragma unroll
                for (int ks = 0; ks < 8; ks++) {
                    const float* r0p = &smA[buf][ks * 8 + tig][0];
                    const float* r1p = &smA[buf][ks * 8 + tig + 4][0];
                    // A fragment: Am[i][k] = chunk[k][Ibase+i]
                    uint32_t a0 = __float_as_uint(r0p[Ibase + gid]);
                    uint32_t a1 = __float_as_uint(r0p[Ibase + gid + 8]);
                    uint32_t a2 = __float_as_uint(r1p[Ibase + gid]);
                    uint32_t a3 = __float_as_uint(r1p[Ibase + gid + 8]);
                    #pragma unroll
                    for (int nt = 0; nt < 8; nt++) {
                        uint32_t b0 = __float_as_uint(r0p[nt * 8 + gid]);
                        uint32_t b1 = __float_as_uint(r1p[nt * 8 + gid]);
                        mma_tf32(dacc[nt], a0, a1, a2, a3, b0, b1);
                    }
                }
            }
            __syncthreads();
        }

        if (compute_warp) {
            float* dst = is_item ? g_g1 : g_gv;
            const int row0 = Ibase + gid;
            #pragma unroll
            for (int nt = 0; nt < 8; nt++) {
                int col = nt * 8 + tig * 2;
                atomicAdd(&dst[row0 * D + col],           dacc[nt][0]);
                atomicAdd(&dst[row0 * D + col + 1],       dacc[nt][1]);
                atomicAdd(&dst[(row0 + 8) * D + col],     dacc[nt][2]);
                atomicAdd(&dst[(row0 + 8) * D + col + 1], dacc[nt][3]);
            }
        }
    } else {
        // ===== pos-loss path: all 4 users per iteration, 20 loads in flight =====
        const int b0 = pos_id * B_PER_BLK;

        for (int i = tid; i < B_PER_BLK * D; i += 256) {
            int bl = i >> 6, d = i & 63;
            smf[i] = userW[(size_t)uids[b0 + bl] * D + d] * hh[d];
        }
        __syncthreads();

        const int warp = tid >> 5, lane = tid & 31;
        float acc = 0.f;

        float2 v0 = ((const float2*)(smf + 0 * D))[lane];
        float2 v1 = ((const float2*)(smf + 1 * D))[lane];
        float2 v2 = ((const float2*)(smf + 2 * D))[lane];
        float2 v3 = ((const float2*)(smf + 3 * D))[lane];
        const int4* pi0 = (const int4*)(pos_iids + (size_t)(b0 + 0) * L);
        const int4* pi1 = (const int4*)(pos_iids + (size_t)(b0 + 1) * L);
        const int4* pi2 = (const int4*)(pos_iids + (size_t)(b0 + 2) * L);
        const int4* pi3 = (const int4*)(pos_iids + (size_t)(b0 + 3) * L);

        for (int q = warp; q < NQUAD; q += 8) {
            int4 iA = pi0[q];
            int4 iB = pi1[q];
            int4 iC = pi2[q];
            int4 iD = pi3[q];

            float2 z = make_float2(0.f, 0.f);
            float2 rA0 = z, rA1 = z, rA2 = z, rA3 = z;
            float2 rB0 = z, rB1 = z, rB2 = z, rB3 = z;
            float2 rC0 = z, rC1 = z, rC2 = z, rC3 = z;
            float2 rD0 = z, rD1 = z, rD2 = z, rD3 = z;
            if (iA.x != PAD_ID) rA0 = ((const float2*)(itemW + (size_t)iA.x * D))[lane];
            if (iA.y != PAD_ID) rA1 = ((const float2*)(itemW + (size_t)iA.y * D))[lane];
            if (iA.z != PAD_ID) rA2 = ((const float2*)(itemW + (size_t)iA.z * D))[lane];
            if (iA.w != PAD_ID) rA3 = ((const float2*)(itemW + (size_t)iA.w * D))[lane];
            if (iB.x != PAD_ID) rB0 = ((const float2*)(itemW + (size_t)iB.x * D))[lane];
            if (iB.y != PAD_ID) rB1 = ((const float2*)(itemW + (size_t)iB.y * D))[lane];
            if (iB.z != PAD_ID) rB2 = ((const float2*)(itemW + (size_t)iB.z * D))[lane];
            if (iB.w != PAD_ID) rB3 = ((const float2*)(itemW + (size_t)iB.w * D))[lane];
            if (iC.x != PAD_ID) rC0 = ((const float2*)(itemW + (size_t)iC.x * D))[lane];
            if (iC.y != PAD_ID) rC1 = ((const float2*)(itemW + (size_t)iC.y * D))[lane];
            if (iC.z != PAD_ID) rC2 = ((const float2*)(itemW + (size_t)iC.z * D))[lane];
            if (iC.w != PAD_ID) rC3 = ((const float2*)(itemW + (size_t)iC.w * D))[lane];
            if (iD.x != PAD_ID) rD0 = ((const float2*)(itemW + (size_t)iD.x * D))[lane];
            if (iD.y != PAD_ID) rD1 = ((const float2*)(itemW + (size_t)iD.y * D))[lane];
            if (iD.z != PAD_ID) rD2 = ((const float2*)(itemW + (size_t)iD.z * D))[lane];
            if (iD.w != PAD_ID) rD3 = ((const float2*)(itemW + (size_t)iD.w * D))[lane];

            float a0 = fmaf(rA0.x, v0.x, rA0.y * v0.y);
            float a1 = fmaf(rA1.x, v0.x, rA1.y * v0.y);
            float a2 = fmaf(rA2.x, v0.x, rA2.y * v0.y);
            float a3 = fmaf(rA3.x, v0.x, rA3.y * v0.y);
            float b0f = fmaf(rB0.x, v1.x, rB0.y * v1.y);
            float b1f = fmaf(rB1.x, v1.x, rB1.y * v1.y);
            float b2f = fmaf(rB2.x, v1.x, rB2.y * v1.y);
            float b3f = fmaf(rB3.x, v1.x, rB3.y * v1.y);
            float c0 = fmaf(rC0.x, v2.x, rC0.y * v2.y);
            float c1 = fmaf(rC1.x, v2.x, rC1.y * v2.y);
            float c2 = fmaf(rC2.x, v2.x, rC2.y * v2.y);
            float c3 = fmaf(rC3.x, v2.x, rC3.y * v2.y);
            float d0 = fmaf(rD0.x, v3.x, rD0.y * v3.y);
            float d1 = fmaf(rD1.x, v3.x, rD1.y * v3.y);
            float d2 = fmaf(rD2.x, v3.x, rD2.y * v3.y);
            float d3 = fmaf(rD3.x, v3.x, rD3.y * v3.y);

            #pragma unroll
            for (int o = 16; o > 0; o >>= 1) {
                a0 += __shfl_xor_sync(0xffffffffu, a0, o);
                b0f += __shfl_xor_sync(0xffffffffu, b0f, o);
                c0 += __shfl_xor_sync(0xffffffffu, c0, o);
                d0 += __shfl_xor_sync(0xffffffffu, d0, o);
                a1 += __shfl_xor_sync(0xffffffffu, a1, o);
                b1f += __shfl_xor_sync(0xffffffffu, b1f, o);
                c1 += __shfl_xor_sync(0xffffffffu, c1, o);
                d1 += __shfl_xor_sync(0xffffffffu, d1, o);
                a2 += __shfl_xor_sync(0xffffffffu, a2, o);
                b2f += __shfl_xor_sync(0xffffffffu, b2f, o);
                c2 += __shfl_xor_sync(0xffffffffu, c2, o);
                d2 += __shfl_xor_sync(0xffffffffu, d2, o);
                a3 += __shfl_xor_sync(0xffffffffu, a3, o);
                b3f += __shfl_xor_sync(0xffffffffu, b3f, o);
                c3 += __shfl_xor_sync(0xffffffffu, c3, o);
                d3 += __shfl_xor_sync(0xffffffffu, d3, o);
            }
            float sq = a0*a0 + a1*a1 + a2*a2 + a3*a3
                     + b0f*b0f + b1f*b1f + b2f*b2f + b3f*b3f
                     + c0*c0 + c1*c1 + c2*c2 + c3*c3
                     + d0*d0 + d1*d1 + d2*d2 + d3*d3;
            float ln = a0 + a1 + a2 + a3 + b0f + b1f + b2f + b3f
                     + c0 + c1 + c2 + c3 + d0 + d1 + d2 + d3;
            acc = fmaf(1.0f - NEGW, sq, fmaf(-2.0f, ln, acc));
        }

        if (lane == 0) warpsum[warp] = acc;
        __syncthreads();
        if (tid == 0) {
            float s = 0.f;
            #pragma unroll
            for (int w = 0; w < 8; w++) s += warpsum[w];
            atomicAdd(&g_pos, s);
        }
    }

    // ================= last block combines + resets =================
    __threadfence();
    __syncthreads();
    if (tid == 0) s_rank = atomicAdd(&g_done, 1u);
    __syncthreads();

    if (s_rank == GRID_TOTAL - 1) {
        volatile float* v1 = g_g1;
        volatile float* v2 = g_gv;
        float s = 0.f;
        for (int e = tid; e < D * D; e += 256)
            s += v1[e] * v2[e];          // both Grams are full matrices now
        smf[tid] = s;
        __syncthreads();
        for (int off = 128; off > 0; off >>= 1) {
            if (tid < off) smf[tid] += smf[tid + off];
            __syncthreads();
        }
        if (tid == 0) {
            out[0] = NEGW * smf[0] + *(volatile float*)&g_pos;
            g_pos = 0.f;
            g_done = 0u;
        }
        for (int e = tid; e < D * D; e += 256) { g_g1[e] = 0.f; g_gv[e] = 0.f; }
    }
}

extern "C" void kernel_launch(void* const* d_in, const int* in_sizes, int n_in,
                              void* d_out, int out_size) {
    const int*   uids     = (const int*)d_in[0];
    const int*   pos_iids = (const int*)d_in[1];
    const float* userW    = (const float*)d_in[2];
    const float* itemW    = (const float*)d_in[3];
    const float* h        = (const float*)d_in[4];
    float* out = (float*)d_out;

    enmf_kernel<<<GRID_TOTAL, 256>>>(uids, pos_iids, userW, itemW, h, out);
}

// round 11
// speedup vs baseline: 2.2108x; 1.1401x over previous
#include <cuda_runtime.h>
#include <cstdint>

#define PAD_ID    100000
#define ITEM_ROWS 100001
#define D   64
#define NB  4096
#define L   200
#define NQUAD (L / 4)
#define NEGW 0.1f

#define NB_G1   296            // item Gram blocks
#define NB_GV   32             // user Gram blocks
#define NB_GRAM (NB_G1 + NB_GV)   // 328
#define NB_POS  1024           // pos-loss blocks
#define B_PER_BLK 4
#define CHUNK   64
#define STRIDE  72             // 8*row+col mod 32 -> conflict-free fragment loads
#define GRID_TOTAL (NB_GRAM + NB_POS)   // 1352

// zero-initialized at module load; last block resets them each run
__device__ float g_g1[D * D];
__device__ float g_gv[D * D];
__device__ float g_pos;
__device__ unsigned int g_done;

__device__ __forceinline__ float tf32r(float x) {
    uint32_t r;
    asm("cvt.rna.tf32.f32 %0, %1;" : "=r"(r) : "f"(x));
    return __uint_as_float(r);
}

__device__ __forceinline__ void mma_tf32(float d[4], uint32_t a0, uint32_t a1,
                                         uint32_t a2, uint32_t a3,
                                         uint32_t b0, uint32_t b1) {
    asm volatile(
        "mma.sync.aligned.m16n8k8.row.col.f32.tf32.tf32.f32 "
        "{%0,%1,%2,%3}, {%4,%5,%6,%7}, {%8,%9}, {%0,%1,%2,%3};\n"
        : "+f"(d[0]), "+f"(d[1]), "+f"(d[2]), "+f"(d[3])
        : "r"(a0), "r"(a1), "r"(a2), "r"(a3), "r"(b0), "r"(b1));
}

__device__ __forceinline__ float dot4(float4 a, float4 b) {
    float s = a.x * b.x;
    s = fmaf(a.y, b.y, s);
    s = fmaf(a.z, b.z, s);
    s = fmaf(a.w, b.w, s);
    return s;
}

__global__ __launch_bounds__(256) void enmf_kernel(
    const int* __restrict__ uids, const int* __restrict__ pos_iids,
    const float* __restrict__ userW, const float* __restrict__ itemW,
    const float* __restrict__ h, float* __restrict__ out)
{
    __shared__ float smA[2][CHUNK][STRIDE];   // 36 KB double buffer (Gram)
    __shared__ float hh[D];
    __shared__ float warpsum[8];
    __shared__ unsigned int s_rank;

    float* smf = &smA[0][0][0];               // flat view for pos path / combine

    const int tid = threadIdx.x;
    const int bid = blockIdx.x;
    if (tid < D) hh[tid] = h[tid];
    __syncthreads();

    // ---- interleave block types so tensor/mem-bound blocks co-reside ----
    int gram_id = -1, pos_id = -1;
    if (bid < NB_GRAM * 4) {
        if ((bid & 3) == 3) gram_id = bid >> 2;
        else                pos_id  = (bid >> 2) * 3 + (bid & 3);
    } else {
        pos_id = NB_GRAM * 3 + (bid - NB_GRAM * 4);
    }

    if (gram_id >= 0) {
        // ========= Gram path: tf32 mma, double-buffered fill =========
        const bool is_item   = (gram_id < NB_G1);
        const int rows_total = is_item ? ITEM_ROWS : NB;
        const int nblk       = is_item ? NB_G1 : NB_GV;
        const int gb         = is_item ? gram_id : gram_id - NB_G1;
        const int per        = (rows_total + nblk - 1) / nblk;
        const int r0         = gb * per;
        const int r1         = min(r0 + per, rows_total);

        const int warp = tid >> 5, lane = tid & 31;
        const int gid  = lane >> 2;       // 0..7
        const int tig  = lane & 3;        // 0..3
        const bool compute_warp = (warp < 4);
        const int Ibase = warp * 16;      // compute warps only

        float dacc[8][4];
        #pragma unroll
        for (int n = 0; n < 8; n++)
            #pragma unroll
            for (int k = 0; k < 4; k++) dacc[n][k] = 0.f;

        const float4* hv4 = (const float4*)hh;

        auto fill = [&](int buf, int base, int lo) {
            for (int i = tid - lo; i < CHUNK * 16; i += 256 - lo) {
                if (i < 0) continue;
                int r = base + (i >> 4);
                int c4 = i & 15;
                float4 v = make_float4(0.f, 0.f, 0.f, 0.f);
                if (r < r1) {
                    if (is_item) {
                        v = ((const float4*)itemW)[(size_t)r * 16 + c4];
                    } else {
                        float4 u = ((const float4*)userW)[(size_t)uids[r] * 16 + c4];
                        float4 hx = hv4[c4];
                        v = make_float4(u.x * hx.x, u.y * hx.y, u.z * hx.z, u.w * hx.w);
                    }
                    v.x = tf32r(v.x); v.y = tf32r(v.y);
                    v.z = tf32r(v.z); v.w = tf32r(v.w);
                }
                ((float4*)&smA[buf][i >> 4][0])[c4] = v;
            }
        };

        fill(0, r0, 0);
        __syncthreads();

        int buf = 0;
        for (int base = r0; base < r1; base += CHUNK, buf ^= 1) {
            if (!compute_warp) {
                if (base + CHUNK < r1) fill(buf ^ 1, base + CHUNK, 128);
            } else {
                #pragma unroll
                for (int ks = 0; ks < 8; ks++) {
                    const float* r0p = &smA[buf][ks * 8 + tig][0];
                    const float* r1p = &smA[buf][ks * 8 + tig + 4][0];
                    uint32_t a0 = __float_as_uint(r0p[Ibase + gid]);
                    uint32_t a1 = __float_as_uint(r0p[Ibase + gid + 8]);
                    uint32_t a2 = __float_as_uint(r1p[Ibase + gid]);
                    uint32_t a3 = __float_as_uint(r1p[Ibase + gid + 8]);
                    #pragma unroll
                    for (int nt = 0; nt < 8; nt++) {
                        uint32_t b0 = __float_as_uint(r0p[nt * 8 + gid]);
                        uint32_t b1 = __float_as_uint(r1p[nt * 8 + gid]);
                        mma_tf32(dacc[nt], a0, a1, a2, a3, b0, b1);
                    }
                }
            }
            __syncthreads();
        }

        if (compute_warp) {
            float* dst = is_item ? g_g1 : g_gv;
            const int row0 = Ibase + gid;
            #pragma unroll
            for (int nt = 0; nt < 8; nt++) {
                int col = nt * 8 + tig * 2;
                atomicAdd(&dst[row0 * D + col],           dacc[nt][0]);
                atomicAdd(&dst[row0 * D + col + 1],       dacc[nt][1]);
                atomicAdd(&dst[(row0 + 8) * D + col],     dacc[nt][2]);
                atomicAdd(&dst[(row0 + 8) * D + col + 1], dacc[nt][3]);
            }
        }
    } else {
        // ===== pos-loss path: 16 lanes/row, 8 rows in flight, 32 SHFL/16 rows =====
        const int b0 = pos_id * B_PER_BLK;

        for (int i = tid; i < B_PER_BLK * D; i += 256) {
            int bl = i >> 6, d = i & 63;
            smf[i] = userW[(size_t)uids[b0 + bl] * D + d] * hh[d];
        }
        __syncthreads();

        const int warp = tid >> 5, lane = tid & 31;
        const int half = lane >> 4;    // which row of each pair
        const int sl   = lane & 15;    // 16-lane slice within a row
        float acc = 0.f;

        float4 v0 = ((const float4*)(smf + 0 * D))[sl];
        float4 v1 = ((const float4*)(smf + 1 * D))[sl];
        float4 v2 = ((const float4*)(smf + 2 * D))[sl];
        float4 v3 = ((const float4*)(smf + 3 * D))[sl];
        const int4* pi0 = (const int4*)(pos_iids + (size_t)(b0 + 0) * L);
        const int4* pi1 = (const int4*)(pos_iids + (size_t)(b0 + 1) * L);
        const int4* pi2 = (const int4*)(pos_iids + (size_t)(b0 + 2) * L);
        const int4* pi3 = (const int4*)(pos_iids + (size_t)(b0 + 3) * L);

        for (int q = warp; q < NQUAD; q += 8) {
            int4 iA = pi0[q];
            int4 iB = pi1[q];
            int4 iC = pi2[q];
            int4 iD = pi3[q];

            // select this half-warp's row for each of the 8 pairs
            int eA0 = half ? iA.y : iA.x;
            int eA1 = half ? iA.w : iA.z;
            int eB0 = half ? iB.y : iB.x;
            int eB1 = half ? iB.w : iB.z;
            int eC0 = half ? iC.y : iC.x;
            int eC1 = half ? iC.w : iC.z;
            int eD0 = half ? iD.y : iD.x;
            int eD1 = half ? iD.w : iD.z;

            // 8 independent LDG.128 gathers (each warp instr covers 2 rows)
            float4 z4 = make_float4(0.f, 0.f, 0.f, 0.f);
            float4 rA0 = z4, rA1 = z4, rB0 = z4, rB1 = z4;
            float4 rC0 = z4, rC1 = z4, rD0 = z4, rD1 = z4;
            if (eA0 != PAD_ID) rA0 = ((const float4*)(itemW + (size_t)eA0 * D))[sl];
            if (eA1 != PAD_ID) rA1 = ((const float4*)(itemW + (size_t)eA1 * D))[sl];
            if (eB0 != PAD_ID) rB0 = ((const float4*)(itemW + (size_t)eB0 * D))[sl];
            if (eB1 != PAD_ID) rB1 = ((const float4*)(itemW + (size_t)eB1 * D))[sl];
            if (eC0 != PAD_ID) rC0 = ((const float4*)(itemW + (size_t)eC0 * D))[sl];
            if (eC1 != PAD_ID) rC1 = ((const float4*)(itemW + (size_t)eC1 * D))[sl];
            if (eD0 != PAD_ID) rD0 = ((const float4*)(itemW + (size_t)eD0 * D))[sl];
            if (eD1 != PAD_ID) rD1 = ((const float4*)(itemW + (size_t)eD1 * D))[sl];

            // 8 independent depth-4 dot chains
            float sA0 = dot4(rA0, v0);
            float sA1 = dot4(rA1, v0);
            float sB0 = dot4(rB0, v1);
            float sB1 = dot4(rB1, v1);
            float sC0 = dot4(rC0, v2);
            float sC1 = dot4(rC1, v2);
            float sD0 = dot4(rD0, v3);
            float sD1 = dot4(rD1, v3);

            // 4-level butterfly within 16-lane halves: reduces 2 rows/instr
            #pragma unroll
            for (int o = 8; o > 0; o >>= 1) {
                sA0 += __shfl_xor_sync(0xffffffffu, sA0, o);
                sB0 += __shfl_xor_sync(0xffffffffu, sB0, o);
                sC0 += __shfl_xor_sync(0xffffffffu, sC0, o);
                sD0 += __shfl_xor_sync(0xffffffffu, sD0, o);
                sA1 += __shfl_xor_sync(0xffffffffu, sA1, o);
                sB1 += __shfl_xor_sync(0xffffffffu, sB1, o);
                sC1 += __shfl_xor_sync(0xffffffffu, sC1, o);
                sD1 += __shfl_xor_sync(0xffffffffu, sD1, o);
            }
            if (sl == 0) {
                float sq = sA0*sA0 + sA1*sA1 + sB0*sB0 + sB1*sB1
                         + sC0*sC0 + sC1*sC1 + sD0*sD0 + sD1*sD1;
                float ln = sA0 + sA1 + sB0 + sB1 + sC0 + sC1 + sD0 + sD1;
                acc = fmaf(1.0f - NEGW, sq, fmaf(-2.0f, ln, acc));
            }
        }

        // acc lives on lanes 0 and 16 of each warp; one butterfly sums the warp
        #pragma unroll
        for (int o = 16; o > 0; o >>= 1)
            acc += __shfl_xor_sync(0xffffffffu, acc, o);
        if (lane == 0) warpsum[warp] = acc;
        __syncthreads();
        if (tid == 0) {
            float s = 0.f;
            #pragma unroll
            for (int w = 0; w < 8; w++) s += warpsum[w];
            atomicAdd(&g_pos, s);
        }
    }

    // ================= last block combines + resets =================
    __threadfence();
    __syncthreads();
    if (tid == 0) s_rank = atomicAdd(&g_done, 1u);
    __syncthreads();

    if (s_rank == GRID_TOTAL - 1) {
        volatile float* v1 = g_g1;
        volatile float* v2 = g_gv;
        float s = 0.f;
        for (int e = tid; e < D * D; e += 256)
            s += v1[e] * v2[e];          // both Grams are full matrices
        smf[tid] = s;
        __syncthreads();
        for (int off = 128; off > 0; off >>= 1) {
            if (tid < off) smf[tid] += smf[tid + off];
            __syncthreads();
        }
        if (tid == 0) {
            out[0] = NEGW * smf[0] + *(volatile float*)&g_pos;
            g_pos = 0.f;
            g_done = 0u;
        }
        for (int e = tid; e < D * D; e += 256) { g_g1[e] = 0.f; g_gv[e] = 0.f; }
    }
}

extern "C" void kernel_launch(void* const* d_in, const int* in_sizes, int n_in,
                              void* d_out, int out_size) {
    const int*   uids     = (const int*)d_in[0];
    const int*   pos_iids = (const int*)d_in[1];
    const float* userW    = (const float*)d_in[2];
    const float* itemW    = (const float*)d_in[3];
    const float* h        = (const float*)d_in[4];
    float* out = (float*)d_out;

    enmf_kernel<<<GRID_TOTAL, 256>>>(uids, pos_iids, userW, itemW, h, out);
}

// round 14
// speedup vs baseline: 2.3128x; 1.0461x over previous
#include <cuda_runtime.h>
#include <cstdint>

#define PAD_ID    100000
#define ITEM_ROWS 100001
#define D   64
#define NB  4096
#define L   200
#define NQUAD (L / 4)
#define NEGW 0.1f

#define NB_G1   296            // item Gram blocks
#define NB_GV   32             // user Gram blocks
#define NB_GRAM (NB_G1 + NB_GV)   // 328
#define NB_POS  1024           // pos-loss blocks
#define B_PER_BLK 4
#define CHUNK   64
#define STRIDE  72             // 8*row+col mod 32 -> conflict-free fragment loads
#define GRID_TOTAL (NB_GRAM + NB_POS)   // 1352

// zero-initialized at module load; last block resets them each run
__device__ float g_g1[D * D];
__device__ float g_gv[D * D];
__device__ float g_pos;
__device__ unsigned int g_done;

__device__ __forceinline__ float tf32r(float x) {
    uint32_t r;
    asm("cvt.rna.tf32.f32 %0, %1;" : "=r"(r) : "f"(x));
    return __uint_as_float(r);
}

__device__ __forceinline__ void mma_tf32(float d[4], uint32_t a0, uint32_t a1,
                                         uint32_t a2, uint32_t a3,
                                         uint32_t b0, uint32_t b1) {
    asm volatile(
        "mma.sync.aligned.m16n8k8.row.col.f32.tf32.tf32.f32 "
        "{%0,%1,%2,%3}, {%4,%5,%6,%7}, {%8,%9}, {%0,%1,%2,%3};\n"
        : "+f"(d[0]), "+f"(d[1]), "+f"(d[2]), "+f"(d[3])
        : "r"(a0), "r"(a1), "r"(a2), "r"(a3), "r"(b0), "r"(b1));
}

__device__ __forceinline__ float dot4(float4 a, float4 b) {
    float s = a.x * b.x;
    s = fmaf(a.y, b.y, s);
    s = fmaf(a.z, b.z, s);
    s = fmaf(a.w, b.w, s);
    return s;
}

__global__ __launch_bounds__(256) void enmf_kernel(
    const int* __restrict__ uids, const int* __restrict__ pos_iids,
    const float* __restrict__ userW, const float* __restrict__ itemW,
    const float* __restrict__ h, float* __restrict__ out)
{
    __shared__ float smA[2][CHUNK][STRIDE];   // 36 KB double buffer (Gram)
    __shared__ int4  s_idx[B_PER_BLK * NQUAD];// 3.2 KB staged indices (pos)
    __shared__ float hh[D];
    __shared__ float warpsum[8];
    __shared__ unsigned int s_rank;

    float* smf = &smA[0][0][0];               // flat view for pos path / combine

    const int tid = threadIdx.x;
    const int bid = blockIdx.x;
    if (tid < D) hh[tid] = h[tid];
    __syncthreads();

    // ---- interleave block types so tensor/mem-bound blocks co-reside ----
    int gram_id = -1, pos_id = -1;
    if (bid < NB_GRAM * 4) {
        if ((bid & 3) == 3) gram_id = bid >> 2;
        else                pos_id  = (bid >> 2) * 3 + (bid & 3);
    } else {
        pos_id = NB_GRAM * 3 + (bid - NB_GRAM * 4);
    }

    if (gram_id >= 0) {
        // ========= Gram path: tf32 mma, double-buffered fill =========
        const bool is_item   = (gram_id < NB_G1);
        const int rows_total = is_item ? ITEM_ROWS : NB;
        const int nblk       = is_item ? NB_G1 : NB_GV;
        const int gb         = is_item ? gram_id : gram_id - NB_G1;
        const int per        = (rows_total + nblk - 1) / nblk;
        const int r0         = gb * per;
        const int r1         = min(r0 + per, rows_total);

        const int warp = tid >> 5, lane = tid & 31;
        const int gid  = lane >> 2;       // 0..7
        const int tig  = lane & 3;        // 0..3
        const bool compute_warp = (warp < 4);
        const int Ibase = warp * 16;      // compute warps only

        float dacc[8][4];
        #pragma unroll
        for (int n = 0; n < 8; n++)
            #pragma unroll
            for (int k = 0; k < 4; k++) dacc[n][k] = 0.f;

        const float4* hv4 = (const float4*)hh;

        auto fill = [&](int buf, int base, int lo) {
            for (int i = tid - lo; i < CHUNK * 16; i += 256 - lo) {
                if (i < 0) continue;
                int r = base + (i >> 4);
                int c4 = i & 15;
                float4 v = make_float4(0.f, 0.f, 0.f, 0.f);
                if (r < r1) {
                    if (is_item) {
                        v = ((const float4*)itemW)[(size_t)r * 16 + c4];
                    } else {
                        float4 u = ((const float4*)userW)[(size_t)uids[r] * 16 + c4];
                        float4 hx = hv4[c4];
                        v = make_float4(u.x * hx.x, u.y * hx.y, u.z * hx.z, u.w * hx.w);
                    }
                    v.x = tf32r(v.x); v.y = tf32r(v.y);
                    v.z = tf32r(v.z); v.w = tf32r(v.w);
                }
                ((float4*)&smA[buf][i >> 4][0])[c4] = v;
            }
        };

        fill(0, r0, 0);
        __syncthreads();

        int buf = 0;
        for (int base = r0; base < r1; base += CHUNK, buf ^= 1) {
            if (!compute_warp) {
                if (base + CHUNK < r1) fill(buf ^ 1, base + CHUNK, 128);
            } else {
                #pragma unroll
                for (int ks = 0; ks < 8; ks++) {
                    const float* r0p = &smA[buf][ks * 8 + tig][0];
                    const float* r1p = &smA[buf][ks * 8 + tig + 4][0];
                    uint32_t a0 = __float_as_uint(r0p[Ibase + gid]);
                    uint32_t a1 = __float_as_uint(r0p[Ibase + gid + 8]);
                    uint32_t a2 = __float_as_uint(r1p[Ibase + gid]);
                    uint32_t a3 = __float_as_uint(r1p[Ibase + gid + 8]);
                    #pragma unroll
                    for (int nt = 0; nt < 8; nt++) {
                        uint32_t b0 = __float_as_uint(r0p[nt * 8 + gid]);
                        uint32_t b1 = __float_as_uint(r1p[nt * 8 + gid]);
                        mma_tf32(dacc[nt], a0, a1, a2, a3, b0, b1);
                    }
                }
            }
            __syncthreads();
        }

        if (compute_warp) {
            float* dst = is_item ? g_g1 : g_gv;
            const int row0 = Ibase + gid;
            #pragma unroll
            for (int nt = 0; nt < 8; nt++) {
                int col = nt * 8 + tig * 2;
                atomicAdd(&dst[row0 * D + col],           dacc[nt][0]);
                atomicAdd(&dst[row0 * D + col + 1],       dacc[nt][1]);
                atomicAdd(&dst[(row0 + 8) * D + col],     dacc[nt][2]);
                atomicAdd(&dst[(row0 + 8) * D + col + 1], dacc[nt][3]);
            }
        }
    } else {
        // ===== pos-loss path: smem-staged indices, 16 lanes/row, 8 rows in flight =====
        const int b0 = pos_id * B_PER_BLK;

        // user vectors (v = u*h) into smem
        for (int i = tid; i < B_PER_BLK * D; i += 256) {
            int bl = i >> 6, d = i & 63;
            smf[i] = userW[(size_t)uids[b0 + bl] * D + d] * hh[d];
        }
        // all 800 indices are contiguous: stage with 200 coalesced int4 loads
        if (tid < B_PER_BLK * NQUAD)
            s_idx[tid] = ((const int4*)(pos_iids + (size_t)b0 * L))[tid];
        __syncthreads();

        const int warp = tid >> 5, lane = tid & 31;
        const int half = lane >> 4;    // which row of each pair
        const int sl   = lane & 15;    // 16-lane slice within a row
        float acc = 0.f;

        float4 v0 = ((const float4*)(smf + 0 * D))[sl];
        float4 v1 = ((const float4*)(smf + 1 * D))[sl];
        float4 v2 = ((const float4*)(smf + 2 * D))[sl];
        float4 v3 = ((const float4*)(smf + 3 * D))[sl];

        #pragma unroll 2
        for (int q = warp; q < NQUAD; q += 8) {
            int4 iA = s_idx[0 * NQUAD + q];
            int4 iB = s_idx[1 * NQUAD + q];
            int4 iC = s_idx[2 * NQUAD + q];
            int4 iD = s_idx[3 * NQUAD + q];

            // select this half-warp's row for each of the 8 pairs
            int eA0 = half ? iA.y : iA.x;
            int eA1 = half ? iA.w : iA.z;
            int eB0 = half ? iB.y : iB.x;
            int eB1 = half ? iB.w : iB.z;
            int eC0 = half ? iC.y : iC.x;
            int eC1 = half ? iC.w : iC.z;
            int eD0 = half ? iD.y : iD.x;
            int eD1 = half ? iD.w : iD.z;

            // 8 independent LDG.128 gathers (each warp instr covers 2 rows)
            float4 z4 = make_float4(0.f, 0.f, 0.f, 0.f);
            float4 rA0 = z4, rA1 = z4, rB0 = z4, rB1 = z4;
            float4 rC0 = z4, rC1 = z4, rD0 = z4, rD1 = z4;
            if (eA0 != PAD_ID) rA0 = ((const float4*)(itemW + (size_t)eA0 * D))[sl];
            if (eA1 != PAD_ID) rA1 = ((const float4*)(itemW + (size_t)eA1 * D))[sl];
            if (eB0 != PAD_ID) rB0 = ((const float4*)(itemW + (size_t)eB0 * D))[sl];
            if (eB1 != PAD_ID) rB1 = ((const float4*)(itemW + (size_t)eB1 * D))[sl];
            if (eC0 != PAD_ID) rC0 = ((const float4*)(itemW + (size_t)eC0 * D))[sl];
            if (eC1 != PAD_ID) rC1 = ((const float4*)(itemW + (size_t)eC1 * D))[sl];
            if (eD0 != PAD_ID) rD0 = ((const float4*)(itemW + (size_t)eD0 * D))[sl];
            if (eD1 != PAD_ID) rD1 = ((const float4*)(itemW + (size_t)eD1 * D))[sl];

            // 8 independent depth-4 dot chains
            float sA0 = dot4(rA0, v0);
            float sA1 = dot4(rA1, v0);
            float sB0 = dot4(rB0, v1);
            float sB1 = dot4(rB1, v1);
            float sC0 = dot4(rC0, v2);
            float sC1 = dot4(rC1, v2);
            float sD0 = dot4(rD0, v3);
            float sD1 = dot4(rD1, v3);

            // 4-level butterfly within 16-lane halves: reduces 2 rows/instr
            #pragma unroll
            for (int o = 8; o > 0; o >>= 1) {
                sA0 += __shfl_xor_sync(0xffffffffu, sA0, o);
                sB0 += __shfl_xor_sync(0xffffffffu, sB0, o);
                sC0 += __shfl_xor_sync(0xffffffffu, sC0, o);
                sD0 += __shfl_xor_sync(0xffffffffu, sD0, o);
                sA1 += __shfl_xor_sync(0xffffffffu, sA1, o);
                sB1 += __shfl_xor_sync(0xffffffffu, sB1, o);
                sC1 += __shfl_xor_sync(0xffffffffu, sC1, o);
                sD1 += __shfl_xor_sync(0xffffffffu, sD1, o);
            }
            if (sl == 0) {
                float sq = sA0*sA0 + sA1*sA1 + sB0*sB0 + sB1*sB1
                         + sC0*sC0 + sC1*sC1 + sD0*sD0 + sD1*sD1;
                float ln = sA0 + sA1 + sB0 + sB1 + sC0 + sC1 + sD0 + sD1;
                acc = fmaf(1.0f - NEGW, sq, fmaf(-2.0f, ln, acc));
            }
        }

        // acc lives on lanes 0 and 16 of each warp; one butterfly sums the warp
        #pragma unroll
        for (int o = 16; o > 0; o >>= 1)
            acc += __shfl_xor_sync(0xffffffffu, acc, o);
        if (lane == 0) warpsum[warp] = acc;
        __syncthreads();
        if (tid == 0) {
            float s = 0.f;
            #pragma unroll
            for (int w = 0; w < 8; w++) s += warpsum[w];
            atomicAdd(&g_pos, s);
        }
    }

    // ================= last block combines + resets =================
    __threadfence();
    __syncthreads();
    if (tid == 0) s_rank = atomicAdd(&g_done, 1u);
    __syncthreads();

    if (s_rank == GRID_TOTAL - 1) {
        volatile float* v1 = g_g1;
        volatile float* v2 = g_gv;
        float s = 0.f;
        for (int e = tid; e < D * D; e += 256)
            s += v1[e] * v2[e];          // both Grams are full matrices
        smf[tid] = s;
        __syncthreads();
        for (int off = 128; off > 0; off >>= 1) {
            if (tid < off) smf[tid] += smf[tid + off];
            __syncthreads();
        }
        if (tid == 0) {
            out[0] = NEGW * smf[0] + *(volatile float*)&g_pos;
            g_pos = 0.f;
            g_done = 0u;
        }
        for (int e = tid; e < D * D; e += 256) { g_g1[e] = 0.f; g_gv[e] = 0.f; }
    }
}

extern "C" void kernel_launch(void* const* d_in, const int* in_sizes, int n_in,
                              void* d_out, int out_size) {
    const int*   uids     = (const int*)d_in[0];
    const int*   pos_iids = (const int*)d_in[1];
    const float* userW    = (const float*)d_in[2];
    const float* itemW    = (const float*)d_in[3];
    const float* h        = (const float*)d_in[4];
    float* out = (float*)d_out;

    enmf_kernel<<<GRID_TOTAL, 256>>>(uids, pos_iids, userW, itemW, h, out);
}